// round 12
// baseline (speedup 1.0000x reference)
#include <cuda_runtime.h>
#include <cstdint>

// Per-row nonlinear scan, w[k+1] = w[k] + a/w[k] - b*x[k], 32768 rows x 1024.
// One thread per row; 32-row x 128-col smem transpose tiles (pad +1).
//
// ARITHMETIC (FROZEN): w = w + a / w - b * xv;  xv read from smem, w written
// to smem, exactly as R1/R2/R11 (rel_err 0.0 every time). Closed lines:
// rcp.approx (R3: 2.05), manual Markstein div (R5/R9: slower), altered tail
// (R8: 9e-2), store-fusion INTO the chain (R6/R7), xv reg-preload (R10: neutral).
//
// Round 12 = R11 with the confirmed phase-halving lever applied again:
//  - TILE 64 -> 128 (NT 16 -> 8): halves syncwarp/loop/phase fixed costs
//  - WPB 4 -> 2 (64-thread blocks, 512 blocks): keeps static smem at 33KB
//    and leaves register room (launch_bounds 64 -> up to 255 regs) for the
//    32-float4 prefetch that lives across the chain.
//  - fused store+commit phase and peeled last tile: R11 verbatim.

#define N_COLS 1024
#define WPB 2
#define TILE 128
#define ROWS_PER_WARP 32

__global__ __launch_bounds__(WPB * 32)
void DDK_77644418777662_kernel(const float* __restrict__ x,
                               const float* __restrict__ alpha,
                               const float* __restrict__ beta,
                               float* __restrict__ out,
                               int rows) {
    // one 32x129 tile per warp (disjoint regions -> __syncwarp suffices)
    __shared__ float sh[WPB][ROWS_PER_WARP][TILE + 1];

    const int warp = threadIdx.x >> 5;
    const int lane = threadIdx.x & 31;
    const int rowBase = (blockIdx.x * WPB + warp) * ROWS_PER_WARP;
    if (rowBase >= rows) return;

    const float a = __ldg(alpha);
    const float b = __ldg(beta);

    const float* xrow = x + (size_t)rowBase * N_COLS;
    float* orow       = out + (size_t)rowBase * N_COLS;

    // cooperative indexing: 32 lanes = 4 rows x 8 float4-chunks; 4 col-quarters
    const int tr = lane >> 3;   // 0..3 row offset within 4-row group
    const int tc = lane & 7;    // 0..7 float4 index within 32-col quarter

    float4 pf[32];              // full next tile: 32 rows x 128 cols / 32 lanes

    // ---- prologue: load tile 0 (32 rows x 128 cols) and commit to smem ----
    #pragma unroll
    for (int g = 0; g < 8; g++)
        #pragma unroll
        for (int h = 0; h < 4; h++)
            pf[g * 4 + h] = *(const float4*)(xrow + (size_t)(g * 4 + tr) * N_COLS
                                             + (tc + 8 * h) * 4);
    #pragma unroll
    for (int g = 0; g < 8; g++) {
        const int r = g * 4 + tr;
        #pragma unroll
        for (int h = 0; h < 4; h++) {
            const int c = (tc + 8 * h) * 4;
            sh[warp][r][c + 0] = pf[g * 4 + h].x;
            sh[warp][r][c + 1] = pf[g * 4 + h].y;
            sh[warp][r][c + 2] = pf[g * 4 + h].z;
            sh[warp][r][c + 3] = pf[g * 4 + h].w;
        }
    }
    __syncwarp();

    float w = 1.0f;

    // ---- main loop: tiles 0..NT-2 (branch-free body) ----
    for (int c0 = 0; c0 < N_COLS - TILE; c0 += TILE) {
        const int next = c0 + TILE;

        // issue next tile's 32 LDG.128 (fly during the ~11500-cycle chain)
        #pragma unroll
        for (int g = 0; g < 8; g++)
            #pragma unroll
            for (int h = 0; h < 4; h++)
                pf[g * 4 + h] = *(const float4*)(xrow + (size_t)(g * 4 + tr) * N_COLS
                                                 + next + (tc + 8 * h) * 4);

        // 128 sequential steps (FROZEN arithmetic, R2/R11's exact smem pattern)
        #pragma unroll
        for (int j = 0; j < TILE; j++) {
            const float xv = sh[warp][lane][j];
            sh[warp][lane][j] = w;
            w = w + a / w - b * xv;
        }
        __syncwarp();

        // fused store + commit: LDS output -> STG -> STS next input (same addr)
        #pragma unroll
        for (int g = 0; g < 8; g++) {
            const int r = g * 4 + tr;
            #pragma unroll
            for (int h = 0; h < 4; h++) {
                const int c = (tc + 8 * h) * 4;
                float4 v;
                v.x = sh[warp][r][c + 0];
                v.y = sh[warp][r][c + 1];
                v.z = sh[warp][r][c + 2];
                v.w = sh[warp][r][c + 3];
                *(float4*)(orow + (size_t)r * N_COLS + c0 + c) = v;
                sh[warp][r][c + 0] = pf[g * 4 + h].x;
                sh[warp][r][c + 1] = pf[g * 4 + h].y;
                sh[warp][r][c + 2] = pf[g * 4 + h].z;
                sh[warp][r][c + 3] = pf[g * 4 + h].w;
            }
        }
        __syncwarp();
    }

    // ---- peeled last tile: chain + store only ----
    {
        const int c0 = N_COLS - TILE;
        #pragma unroll
        for (int j = 0; j < TILE; j++) {
            const float xv = sh[warp][lane][j];
            sh[warp][lane][j] = w;
            w = w + a / w - b * xv;     // final update is dead code (harmless)
        }
        __syncwarp();
        #pragma unroll
        for (int g = 0; g < 8; g++) {
            const int r = g * 4 + tr;
            #pragma unroll
            for (int h = 0; h < 4; h++) {
                const int c = (tc + 8 * h) * 4;
                float4 v;
                v.x = sh[warp][r][c + 0];
                v.y = sh[warp][r][c + 1];
                v.z = sh[warp][r][c + 2];
                v.w = sh[warp][r][c + 3];
                *(float4*)(orow + (size_t)r * N_COLS + c0 + c) = v;
            }
        }
    }
}

extern "C" void kernel_launch(void* const* d_in, const int* in_sizes, int n_in,
                              void* d_out, int out_size) {
    const float* x     = (const float*)d_in[0];
    const float* alpha = (const float*)d_in[1];
    const float* beta  = (const float*)d_in[2];
    float* out         = (float*)d_out;

    const int rows = out_size / N_COLS;                      // 32768
    const int rowsPerBlock = WPB * ROWS_PER_WARP;            // 64
    const int blocks = (rows + rowsPerBlock - 1) / rowsPerBlock;  // 512

    DDK_77644418777662_kernel<<<blocks, WPB * 32>>>(x, alpha, beta, out, rows);
}

// round 13
// speedup vs baseline: 1.4822x; 1.4822x over previous
#include <cuda_runtime.h>
#include <cstdint>

// Per-row nonlinear scan, w[k+1] = w[k] + a/w[k] - b*x[k], 32768 rows x 1024.
//
// ARITHMETIC (FROZEN): w = w + a / w - b * xv; xv from smem, w to smem,
// exact pattern of R1/R2/R11 (rel_err 0.0 every time). Closed lines:
// rcp.approx (R3), manual Markstein (R5/R9), altered tail (R8), in-warp
// store fusion (R6/R7), xv reg-preload (R10), TILE=128 (R12: I$ blowout).
//
// Round 13: WARP SPECIALIZATION. Block = 2 compute warps + 1 DMA warp.
// Compute warps run ONLY the 64-step chain per tile + 1 __syncthreads().
// The DMA warp overlaps ALL memory phases (LDG next tile, STG prev outputs,
// STS commit) with the ~5800-cycle chains, on double-buffered 32x65 tiles.
// 4 blocks/SM is mandatory (512 blocks, single wave) -> launch_bounds(96,4).

#define N_COLS 1024
#define TILE 64
#define NT (N_COLS / TILE)   // 16
#define CW 2                 // compute warps per block
#define THREADS ((CW + 1) * 32)

__global__ __launch_bounds__(THREADS, 4)
void DDK_77644418777662_kernel(const float* __restrict__ x,
                               const float* __restrict__ alpha,
                               const float* __restrict__ beta,
                               float* __restrict__ out) {
    // per compute warp: double-buffered 32x(64+1) tile (pad -> conflict-free)
    __shared__ float sh[CW][2][32][TILE + 1];

    const int wid  = threadIdx.x >> 5;
    const int lane = threadIdx.x & 31;
    const int blockRow = blockIdx.x * (CW * 32);

    if (wid < CW) {
        // ======================= COMPUTE WARP =======================
        const float a = __ldg(alpha);
        const float b = __ldg(beta);
        float w = 1.0f;

        __syncthreads();                       // tile 0 committed by DMA warp
        for (int t = 0; t < NT; t++) {
            const int p = t & 1;
            #pragma unroll
            for (int j = 0; j < TILE; j++) {   // FROZEN chain, R11's pattern
                const float xv = sh[wid][p][lane][j];
                sh[wid][p][lane][j] = w;
                w = w + a / w - b * xv;
            }
            __syncthreads();
        }
        // DMA warp stores the last tile; compute warps are done.
    } else {
        // ========================= DMA WARP =========================
        const int tr = lane >> 3;   // 0..3
        const int tc = lane & 7;    // 0..7

        const float* xw[CW];
        float*       ow[CW];
        #pragma unroll
        for (int cw = 0; cw < CW; cw++) {
            xw[cw] = x   + (size_t)(blockRow + cw * 32) * N_COLS;
            ow[cw] = out + (size_t)(blockRow + cw * 32) * N_COLS;
        }

        // ---- prologue: load tile 0 into buffer 0 for both compute warps ----
        #pragma unroll
        for (int cw = 0; cw < CW; cw++) {
            float4 pf[16];
            #pragma unroll
            for (int g = 0; g < 8; g++)
                #pragma unroll
                for (int h = 0; h < 2; h++)
                    pf[g * 2 + h] = *(const float4*)(xw[cw]
                        + (size_t)(g * 4 + tr) * N_COLS + (tc + 8 * h) * 4);
            #pragma unroll
            for (int g = 0; g < 8; g++) {
                const int r = g * 4 + tr;
                #pragma unroll
                for (int h = 0; h < 2; h++) {
                    const int c = (tc + 8 * h) * 4;
                    sh[cw][0][r][c + 0] = pf[g * 2 + h].x;
                    sh[cw][0][r][c + 1] = pf[g * 2 + h].y;
                    sh[cw][0][r][c + 2] = pf[g * 2 + h].z;
                    sh[cw][0][r][c + 3] = pf[g * 2 + h].w;
                }
            }
        }
        __syncthreads();

        // ---- main loop: while compute chains on buffer p=t&1, service q ----
        for (int t = 0; t < NT; t++) {
            const int q = (t & 1) ^ 1;         // free buffer

            #pragma unroll
            for (int cw = 0; cw < CW; cw++) {
                float4 pf[16];
                // issue tile t+1 LDGs first (fly during store phase)
                if (t + 1 < NT) {
                    const int cn = (t + 1) * TILE;
                    #pragma unroll
                    for (int g = 0; g < 8; g++)
                        #pragma unroll
                        for (int h = 0; h < 2; h++)
                            pf[g * 2 + h] = *(const float4*)(xw[cw]
                                + (size_t)(g * 4 + tr) * N_COLS + cn + (tc + 8 * h) * 4);
                }
                // store tile t-1 outputs from buffer q
                if (t > 0) {
                    const int c0 = (t - 1) * TILE;
                    #pragma unroll
                    for (int g = 0; g < 8; g++) {
                        const int r = g * 4 + tr;
                        #pragma unroll
                        for (int h = 0; h < 2; h++) {
                            const int c = (tc + 8 * h) * 4;
                            float4 v;
                            v.x = sh[cw][q][r][c + 0];
                            v.y = sh[cw][q][r][c + 1];
                            v.z = sh[cw][q][r][c + 2];
                            v.w = sh[cw][q][r][c + 3];
                            *(float4*)(ow[cw] + (size_t)r * N_COLS + c0 + c) = v;
                        }
                    }
                }
                // commit tile t+1 inputs into buffer q (after stores read it)
                if (t + 1 < NT) {
                    #pragma unroll
                    for (int g = 0; g < 8; g++) {
                        const int r = g * 4 + tr;
                        #pragma unroll
                        for (int h = 0; h < 2; h++) {
                            const int c = (tc + 8 * h) * 4;
                            sh[cw][q][r][c + 0] = pf[g * 2 + h].x;
                            sh[cw][q][r][c + 1] = pf[g * 2 + h].y;
                            sh[cw][q][r][c + 2] = pf[g * 2 + h].z;
                            sh[cw][q][r][c + 3] = pf[g * 2 + h].w;
                        }
                    }
                }
            }
            __syncthreads();
        }

        // ---- epilogue: store last tile's outputs (buffer (NT-1)&1 = 1) ----
        {
            const int c0 = (NT - 1) * TILE;
            #pragma unroll
            for (int cw = 0; cw < CW; cw++)
                #pragma unroll
                for (int g = 0; g < 8; g++) {
                    const int r = g * 4 + tr;
                    #pragma unroll
                    for (int h = 0; h < 2; h++) {
                        const int c = (tc + 8 * h) * 4;
                        float4 v;
                        v.x = sh[cw][1][r][c + 0];
                        v.y = sh[cw][1][r][c + 1];
                        v.z = sh[cw][1][r][c + 2];
                        v.w = sh[cw][1][r][c + 3];
                        *(float4*)(ow[cw] + (size_t)r * N_COLS + c0 + c) = v;
                    }
                }
        }
    }
}

extern "C" void kernel_launch(void* const* d_in, const int* in_sizes, int n_in,
                              void* d_out, int out_size) {
    const float* x     = (const float*)d_in[0];
    const float* alpha = (const float*)d_in[1];
    const float* beta  = (const float*)d_in[2];
    float* out         = (float*)d_out;

    const int rows = out_size / N_COLS;                 // 32768
    const int blocks = rows / (CW * 32);                // 512 (exact)

    DDK_77644418777662_kernel<<<blocks, THREADS>>>(x, alpha, beta, out);
}